// round 5
// baseline (speedup 1.0000x reference)
#include <cuda_runtime.h>
#include <cuda_bf16.h>
#include <cstdint>

#define NN 50000
#define NE 800000
#define DD 128

// Scratch (static __device__ arrays: allocation-free)
static __device__ float g_agg[(size_t)NN * DD];
static __device__ float g_x1 [(size_t)NN * DD];
static __device__ float g_x2 [(size_t)NN * DD];
static __device__ float g_invdeg[NN];
static __device__ int   g_deg[NN];
static __device__ int   g_rowptr[NN + 1];
static __device__ int   g_cursor[NN];
static __device__ int   g_csr_col[NE];

// ---------------- degree / CSR build ----------------
__global__ void k_zero_deg() {
    int i = blockIdx.x * blockDim.x + threadIdx.x;
    if (i < NN) g_deg[i] = 0;
}
__global__ void k_count_deg(const int* __restrict__ row) {
    int e = blockIdx.x * blockDim.x + threadIdx.x;
    if (e < NE) atomicAdd(&g_deg[row[e]], 1);
}
__global__ void __launch_bounds__(1024) k_scan() {
    __shared__ int ps[1024];
    const int T = 1024;
    int t = threadIdx.x;
    const int chunk = (NN + T - 1) / T;
    int beg = t * chunk;
    int end = min(beg + chunk, NN);
    int s = 0;
    for (int i = beg; i < end; i++) s += g_deg[i];
    ps[t] = s;
    __syncthreads();
    for (int d = 1; d < T; d <<= 1) {
        int v = (t >= d) ? ps[t - d] : 0;
        __syncthreads();
        ps[t] += v;
        __syncthreads();
    }
    int off = ps[t] - s;
    for (int i = beg; i < end; i++) {
        int dg = g_deg[i];
        g_rowptr[i] = off;
        g_cursor[i] = off;
        g_invdeg[i] = 1.0f / fmaxf((float)dg, 1.0f);
        off += dg;
    }
    if (t == T - 1) g_rowptr[NN] = off;
}
__global__ void k_fill(const int* __restrict__ row, const int* __restrict__ col) {
    int e = blockIdx.x * blockDim.x + threadIdx.x;
    if (e < NE) {
        int r = row[e];
        int p = atomicAdd(&g_cursor[r], 1);
        g_csr_col[p] = col[e];
    }
}

// ---------------- gather: agg[n] = invdeg[n] * sum_nbr maybe_relu(src[c]) ----------------
// One warp per node; lane owns one float4 (4 feature cols).
// Indices staged via one coalesced load per 32 neighbors + shfl broadcast;
// 4 independent accumulators give MLP>=4 on the feature loads.
template <bool RELU>
__global__ void __launch_bounds__(256) k_gather(const float* __restrict__ src) {
    int w    = (blockIdx.x * blockDim.x + threadIdx.x) >> 5;
    int lane = threadIdx.x & 31;
    if (w >= NN) return;
    const int beg = g_rowptr[w];
    const int deg = g_rowptr[w + 1] - beg;

    float4 a0 = make_float4(0.f, 0.f, 0.f, 0.f);
    float4 a1 = a0, a2 = a0, a3 = a0;

    for (int base = 0; base < deg; base += 32) {
        int n = min(32, deg - base);
        int myIdx = (base + lane < deg) ? __ldg(g_csr_col + beg + base + lane) : 0;
        int j = 0;
        for (; j + 3 < n; j += 4) {
            int c0 = __shfl_sync(0xffffffffu, myIdx, j);
            int c1 = __shfl_sync(0xffffffffu, myIdx, j + 1);
            int c2 = __shfl_sync(0xffffffffu, myIdx, j + 2);
            int c3 = __shfl_sync(0xffffffffu, myIdx, j + 3);
            float4 v0 = __ldg((const float4*)(src + (size_t)c0 * DD) + lane);
            float4 v1 = __ldg((const float4*)(src + (size_t)c1 * DD) + lane);
            float4 v2 = __ldg((const float4*)(src + (size_t)c2 * DD) + lane);
            float4 v3 = __ldg((const float4*)(src + (size_t)c3 * DD) + lane);
            if (RELU) {
                v0.x = fmaxf(v0.x, 0.f); v0.y = fmaxf(v0.y, 0.f);
                v0.z = fmaxf(v0.z, 0.f); v0.w = fmaxf(v0.w, 0.f);
                v1.x = fmaxf(v1.x, 0.f); v1.y = fmaxf(v1.y, 0.f);
                v1.z = fmaxf(v1.z, 0.f); v1.w = fmaxf(v1.w, 0.f);
                v2.x = fmaxf(v2.x, 0.f); v2.y = fmaxf(v2.y, 0.f);
                v2.z = fmaxf(v2.z, 0.f); v2.w = fmaxf(v2.w, 0.f);
                v3.x = fmaxf(v3.x, 0.f); v3.y = fmaxf(v3.y, 0.f);
                v3.z = fmaxf(v3.z, 0.f); v3.w = fmaxf(v3.w, 0.f);
            }
            a0.x += v0.x; a0.y += v0.y; a0.z += v0.z; a0.w += v0.w;
            a1.x += v1.x; a1.y += v1.y; a1.z += v1.z; a1.w += v1.w;
            a2.x += v2.x; a2.y += v2.y; a2.z += v2.z; a2.w += v2.w;
            a3.x += v3.x; a3.y += v3.y; a3.z += v3.z; a3.w += v3.w;
        }
        for (; j < n; j++) {
            int c0 = __shfl_sync(0xffffffffu, myIdx, j);
            float4 v0 = __ldg((const float4*)(src + (size_t)c0 * DD) + lane);
            if (RELU) {
                v0.x = fmaxf(v0.x, 0.f); v0.y = fmaxf(v0.y, 0.f);
                v0.z = fmaxf(v0.z, 0.f); v0.w = fmaxf(v0.w, 0.f);
            }
            a0.x += v0.x; a0.y += v0.y; a0.z += v0.z; a0.w += v0.w;
        }
    }

    float s = g_invdeg[w];
    float4 acc;
    acc.x = ((a0.x + a1.x) + (a2.x + a3.x)) * s;
    acc.y = ((a0.y + a1.y) + (a2.y + a3.y)) * s;
    acc.z = ((a0.z + a1.z) + (a2.z + a3.z)) * s;
    acc.w = ((a0.w + a1.w) + (a2.w + a3.w)) * s;
    ((float4*)(g_agg + (size_t)w * DD))[lane] = acc;
}

// ================= mma.sync bf16-split GEMM =================
// out[i][j] = sum_k A[i][k]*B[j][k] + bias[j] (+ h[i][j] if RES)
//   A[i][k<128]  = g_agg[i][k] ;  A[i][k>=128] = maybe_relu(h[i][k-128])
//   B[j][k<128]  = Wl[j][k]    ;  B[j][k>=128] = Wr[j][k-128]   (K-major already)
// Split v = hi(bf16) + lo(bf16); D = AhiBhi + AhiBlo + AloBhi   (err ~1e-5)
// K chunked by 64; planes: 128 rows x 64 bf16 (128B rows, SW128 XOR swizzle).

#define OFF_BIAS 0
#define OFF_AHI  1024
#define OFF_ALO  (1024 + 16384)
#define OFF_BHI  (1024 + 32768)
#define OFF_BLO  (1024 + 49152)
#define SMEM_GEMM (1024 + 65536)

__device__ __forceinline__ uint32_t s2u(const void* p) {
    uint32_t a;
    asm("{ .reg .u64 t; cvta.to.shared.u64 t, %1; cvt.u32.u64 %0, t; }" : "=r"(a) : "l"(p));
    return a;
}
__device__ __forceinline__ void ldsm4(uint32_t& r0, uint32_t& r1, uint32_t& r2, uint32_t& r3,
                                      uint32_t addr) {
    asm volatile("ldmatrix.sync.aligned.m8n8.x4.shared.b16 {%0,%1,%2,%3}, [%4];"
                 : "=r"(r0), "=r"(r1), "=r"(r2), "=r"(r3) : "r"(addr));
}
__device__ __forceinline__ void mma16816(float* d, const uint32_t* a, const uint32_t* b) {
    asm volatile("mma.sync.aligned.m16n8k16.row.col.f32.bf16.bf16.f32 "
                 "{%0,%1,%2,%3}, {%4,%5,%6,%7}, {%8,%9}, {%0,%1,%2,%3};"
                 : "+f"(d[0]), "+f"(d[1]), "+f"(d[2]), "+f"(d[3])
                 : "r"(a[0]), "r"(a[1]), "r"(a[2]), "r"(a[3]), "r"(b[0]), "r"(b[1]));
}
// per-lane ldmatrix address for a 16(row)x16(k) tile at (r0,k0) in a swizzled plane
__device__ __forceinline__ uint32_t tile_addr(uint32_t planeBase, int lane, int r0, int k0) {
    int rr = r0 + (lane & 15);
    int kk = k0 + ((lane >> 4) << 3);
    uint32_t off = rr * 128 + kk * 2;
    return planeBase + (off ^ ((off >> 3) & 0x70));
}
// split one float4 into bf16 hi/lo planes (8B each), swizzled store
__device__ __forceinline__ void st_hl(char* hiBase, char* loBase, int row, int q, float4 v) {
    __nv_bfloat16 hx = __float2bfloat16_rn(v.x);
    __nv_bfloat16 hy = __float2bfloat16_rn(v.y);
    __nv_bfloat16 hz = __float2bfloat16_rn(v.z);
    __nv_bfloat16 hw = __float2bfloat16_rn(v.w);
    __nv_bfloat16 lx = __float2bfloat16_rn(v.x - __bfloat162float(hx));
    __nv_bfloat16 ly = __float2bfloat16_rn(v.y - __bfloat162float(hy));
    __nv_bfloat16 lz = __float2bfloat16_rn(v.z - __bfloat162float(hz));
    __nv_bfloat16 lw = __float2bfloat16_rn(v.w - __bfloat162float(hw));
    __nv_bfloat162 H01, H23, L01, L23;
    H01.x = hx; H01.y = hy; H23.x = hz; H23.y = hw;
    L01.x = lx; L01.y = ly; L23.x = lz; L23.y = lw;
    int off = row * 128 + q * 8;
    int sw = off ^ ((off >> 3) & 0x70);
    uint2 Hw, Lw;
    Hw.x = *(uint32_t*)&H01; Hw.y = *(uint32_t*)&H23;
    Lw.x = *(uint32_t*)&L01; Lw.y = *(uint32_t*)&L23;
    *(uint2*)(hiBase + sw) = Hw;
    *(uint2*)(loBase + sw) = Lw;
}

template <bool RELU, bool RES>
__global__ void __launch_bounds__(256)
k_gemm_mma(const float* __restrict__ h, const float* __restrict__ Wl,
           const float* __restrict__ Wr, const float* __restrict__ bias,
           float* __restrict__ out)
{
    extern __shared__ char smem[];
    const uint32_t sb = s2u(smem);
    const int t    = threadIdx.x;
    const int wid  = t >> 5;
    const int lane = t & 31;
    const int rowBase = blockIdx.x * 128;
    const int wm = (wid >> 2) * 64;   // warp m-base (0 or 64)
    const int wn = (wid & 3) * 32;    // warp n-base (0,32,64,96)

    if (t < 128) ((float*)(smem + OFF_BIAS))[t] = bias[t];

    float acc[4][4][4];   // [mtile][ntile][4]
#pragma unroll
    for (int i = 0; i < 4; i++)
#pragma unroll
        for (int j = 0; j < 4; j++)
#pragma unroll
            for (int q = 0; q < 4; q++) acc[i][j][q] = 0.f;

    for (int c = 0; c < 4; c++) {
        if (c > 0) __syncthreads();   // previous compute done before refill
        // ---- fill chunk c (K = [c*64, c*64+64)) ----
#pragma unroll
        for (int u = 0; u < 8; u++) {
            int idx = t + u * 256;        // 0..2047 float4 slots (128 rows x 16)
            int row = idx >> 4;
            int q   = idx & 15;
            int gi  = rowBase + row;
            float4 va = make_float4(0.f, 0.f, 0.f, 0.f);
            if (gi < NN) {
                if (c < 2) {
                    va = __ldg((const float4*)(g_agg + (size_t)gi * DD + c * 64) + q);
                } else {
                    va = __ldg((const float4*)(h + (size_t)gi * DD + (c - 2) * 64) + q);
                    if (RELU) {
                        va.x = fmaxf(va.x, 0.f); va.y = fmaxf(va.y, 0.f);
                        va.z = fmaxf(va.z, 0.f); va.w = fmaxf(va.w, 0.f);
                    }
                }
            }
            st_hl(smem + OFF_AHI, smem + OFF_ALO, row, q, va);
            const float* W = (c < 2) ? Wl : Wr;
            float4 vb = __ldg((const float4*)(W + (size_t)row * DD + (c & 1) * 64) + q);
            st_hl(smem + OFF_BHI, smem + OFF_BLO, row, q, vb);
        }
        __syncthreads();

        // ---- compute: 4 k-steps of 16 ----
#pragma unroll
        for (int ks = 0; ks < 4; ks++) {
            const int k0 = ks * 16;
            // B fragments: 2 ldsm4 per plane cover all 4 n-tiles (n=wn..wn+31)
            uint32_t bhi[4][2], blo[4][2];
#pragma unroll
            for (int p = 0; p < 2; p++) {
                uint32_t r0, r1, r2, r3;
                ldsm4(r0, r1, r2, r3, tile_addr(sb + OFF_BHI, lane, wn + p * 16, k0));
                bhi[2 * p][0] = r0;     bhi[2 * p][1] = r2;
                bhi[2 * p + 1][0] = r1; bhi[2 * p + 1][1] = r3;
                ldsm4(r0, r1, r2, r3, tile_addr(sb + OFF_BLO, lane, wn + p * 16, k0));
                blo[2 * p][0] = r0;     blo[2 * p][1] = r2;
                blo[2 * p + 1][0] = r1; blo[2 * p + 1][1] = r3;
            }
#pragma unroll
            for (int i = 0; i < 4; i++) {
                uint32_t ahi[4], alo[4];
                ldsm4(ahi[0], ahi[1], ahi[2], ahi[3],
                      tile_addr(sb + OFF_AHI, lane, wm + i * 16, k0));
                ldsm4(alo[0], alo[1], alo[2], alo[3],
                      tile_addr(sb + OFF_ALO, lane, wm + i * 16, k0));
#pragma unroll
                for (int j = 0; j < 4; j++) {
                    mma16816(acc[i][j], ahi, bhi[j]);
                    mma16816(acc[i][j], ahi, blo[j]);
                    mma16816(acc[i][j], alo, bhi[j]);
                }
            }
        }
    }

    // ---- epilogue: bias (+ residual), direct register->gmem ----
    const float* bsh = (const float*)(smem + OFF_BIAS);
    const int tr = lane >> 2;         // 0..7
    const int tc = (lane & 3) * 2;    // 0,2,4,6
#pragma unroll
    for (int i = 0; i < 4; i++) {
#pragma unroll
        for (int half = 0; half < 2; half++) {
            int gi = rowBase + wm + i * 16 + tr + half * 8;
            if (gi >= NN) continue;
#pragma unroll
            for (int j = 0; j < 4; j++) {
                int col = wn + j * 8 + tc;
                float2 o;
                o.x = acc[i][j][half * 2]     + bsh[col];
                o.y = acc[i][j][half * 2 + 1] + bsh[col + 1];
                if (RES) {
                    float2 rv = __ldg((const float2*)(h + (size_t)gi * DD + col));
                    o.x += rv.x; o.y += rv.y;
                }
                *(float2*)(out + (size_t)gi * DD + col) = o;
            }
        }
    }
}

// ---------------- launch ----------------
extern "C" void kernel_launch(void* const* d_in, const int* in_sizes, int n_in,
                              void* d_out, int out_size) {
    const float* x    = (const float*)d_in[0];
    const int*   erow = (const int*)  d_in[1];
    const int*   ecol = (const int*)  d_in[2];
    const float* Wl0 = (const float*)d_in[3];
    const float* Wr0 = (const float*)d_in[4];
    const float* b0  = (const float*)d_in[5];
    const float* Wl1 = (const float*)d_in[6];
    const float* Wr1 = (const float*)d_in[7];
    const float* b1  = (const float*)d_in[8];
    const float* Wl2 = (const float*)d_in[9];
    const float* Wr2 = (const float*)d_in[10];
    const float* b2  = (const float*)d_in[11];
    float* out = (float*)d_out;

    float *p_x1 = nullptr, *p_x2 = nullptr;
    cudaGetSymbolAddress((void**)&p_x1, g_x1);
    cudaGetSymbolAddress((void**)&p_x2, g_x2);

    cudaFuncSetAttribute(k_gemm_mma<false, false>,
                         cudaFuncAttributeMaxDynamicSharedMemorySize, SMEM_GEMM);
    cudaFuncSetAttribute(k_gemm_mma<true, true>,
                         cudaFuncAttributeMaxDynamicSharedMemorySize, SMEM_GEMM);

    const int nodeBlocks   = (NN + 255) / 256;
    const int edgeBlocks   = (NE + 255) / 256;
    const int gatherBlocks = (NN * 32 + 255) / 256;   // 6250
    const int gemmBlocks   = (NN + 127) / 128;        // 391

    // CSR build
    k_zero_deg<<<nodeBlocks, 256>>>();
    k_count_deg<<<edgeBlocks, 256>>>(erow);
    k_scan<<<1, 1024>>>();
    k_fill<<<edgeBlocks, 256>>>(erow, ecol);

    // ---- layer 0: x1 = sage(x) ----
    k_gather<false><<<gatherBlocks, 256>>>(x);
    k_gemm_mma<false, false><<<gemmBlocks, 256, SMEM_GEMM>>>(x, Wl0, Wr0, b0, p_x1);

    // ---- layer 1: x2 = sage(relu(x1)) + x1 ----
    k_gather<true><<<gatherBlocks, 256>>>(p_x1);
    k_gemm_mma<true, true><<<gemmBlocks, 256, SMEM_GEMM>>>(p_x1, Wl1, Wr1, b1, p_x2);

    // ---- layer 2: out = sage(relu(x2)) + x2 ----
    k_gather<true><<<gatherBlocks, 256>>>(p_x2);
    k_gemm_mma<true, true><<<gemmBlocks, 256, SMEM_GEMM>>>(p_x2, Wl2, Wr2, b2, out);
}

// round 6
// speedup vs baseline: 1.1578x; 1.1578x over previous
#include <cuda_runtime.h>
#include <cuda_bf16.h>
#include <cstdint>

#define NN 50000
#define NE 800000
#define DD 128
#define NTILES 391   // ceil(NN/128)

// Scratch (static __device__ arrays: allocation-free)
static __device__ float g_x1 [(size_t)NN * DD];
static __device__ float g_x2 [(size_t)NN * DD];
static __device__ float g_invdeg[NN];
static __device__ int   g_deg[NN];
static __device__ int   g_rowptr[NN + 1];
static __device__ int   g_cursor[NN];
static __device__ int   g_csr_col[NE];
// bf16 hi/lo planes, pre-swizzled 16KB tile-planes (128 rows x 128B)
static __device__ uint4 g_aggh4[2 * NTILES * 1024];   // agg chunks 0-1
static __device__ uint4 g_aggl4[2 * NTILES * 1024];
static __device__ uint4 g_wh4[12 * 1024];             // 3 layers x 4 chunks
static __device__ uint4 g_wl4[12 * 1024];

// split one float4 into bf16 hi/lo, swizzled 8B stores at (row, q)
__device__ __forceinline__ void st_hl(char* hiBase, char* loBase, int row, int q, float4 v) {
    __nv_bfloat16 hx = __float2bfloat16_rn(v.x);
    __nv_bfloat16 hy = __float2bfloat16_rn(v.y);
    __nv_bfloat16 hz = __float2bfloat16_rn(v.z);
    __nv_bfloat16 hw = __float2bfloat16_rn(v.w);
    __nv_bfloat16 lx = __float2bfloat16_rn(v.x - __bfloat162float(hx));
    __nv_bfloat16 ly = __float2bfloat16_rn(v.y - __bfloat162float(hy));
    __nv_bfloat16 lz = __float2bfloat16_rn(v.z - __bfloat162float(hz));
    __nv_bfloat16 lw = __float2bfloat16_rn(v.w - __bfloat162float(hw));
    __nv_bfloat162 H01, H23, L01, L23;
    H01.x = hx; H01.y = hy; H23.x = hz; H23.y = hw;
    L01.x = lx; L01.y = ly; L23.x = lz; L23.y = lw;
    int off = row * 128 + q * 8;
    int sw = off ^ ((off >> 3) & 0x70);
    uint2 Hw, Lw;
    Hw.x = *(uint32_t*)&H01; Hw.y = *(uint32_t*)&H23;
    Lw.x = *(uint32_t*)&L01; Lw.y = *(uint32_t*)&L23;
    *(uint2*)(hiBase + sw) = Hw;
    *(uint2*)(loBase + sw) = Lw;
}

// ---------------- degree / CSR build ----------------
__global__ void k_zero_deg() {
    int i = blockIdx.x * blockDim.x + threadIdx.x;
    if (i < NN) g_deg[i] = 0;
}
__global__ void k_count_deg(const int* __restrict__ row) {
    int e = blockIdx.x * blockDim.x + threadIdx.x;
    if (e < NE) atomicAdd(&g_deg[row[e]], 1);
}
__global__ void __launch_bounds__(1024) k_scan() {
    __shared__ int ps[1024];
    const int T = 1024;
    int t = threadIdx.x;
    const int chunk = (NN + T - 1) / T;
    int beg = t * chunk;
    int end = min(beg + chunk, NN);
    int s = 0;
    for (int i = beg; i < end; i++) s += g_deg[i];
    ps[t] = s;
    __syncthreads();
    for (int d = 1; d < T; d <<= 1) {
        int v = (t >= d) ? ps[t - d] : 0;
        __syncthreads();
        ps[t] += v;
        __syncthreads();
    }
    int off = ps[t] - s;
    for (int i = beg; i < end; i++) {
        int dg = g_deg[i];
        g_rowptr[i] = off;
        g_cursor[i] = off;
        g_invdeg[i] = 1.0f / fmaxf((float)dg, 1.0f);
        off += dg;
    }
    if (t == T - 1) g_rowptr[NN] = off;
}
__global__ void k_fill(const int* __restrict__ row, const int* __restrict__ col) {
    int e = blockIdx.x * blockDim.x + threadIdx.x;
    if (e < NE) {
        int r = row[e];
        int p = atomicAdd(&g_cursor[r], 1);
        g_csr_col[p] = col[e];
    }
}

// ---------------- W pre-split: 4 swizzled bf16 hi/lo tile-planes per layer ----------------
__global__ void k_buildW(const float* __restrict__ Wl, const float* __restrict__ Wr, int layer) {
    int idx = blockIdx.x * blockDim.x + threadIdx.x;   // 0..8191
    if (idx >= 8192) return;
    int w    = idx >> 12;       // 0: Wl, 1: Wr
    int rem  = idx & 4095;
    int row  = rem >> 5;        // out-dim 0..127
    int slot = rem & 31;        // float4 slot across 128 in-dims
    int chunk = w * 2 + (slot >> 4);
    int q     = slot & 15;
    const float* W = w ? Wr : Wl;
    float4 v = __ldg((const float4*)(W + (size_t)row * DD) + slot);
    char* hb = (char*)g_wh4 + (size_t)(layer * 4 + chunk) * 16384;
    char* lb = (char*)g_wl4 + (size_t)(layer * 4 + chunk) * 16384;
    st_hl(hb, lb, row, q, v);
}

// ---------------- gather: agg planes = split(invdeg[n] * sum_nbr maybe_relu(src[c])) ----------------
// One warp per node; lane owns one float4. 4 independent index+feature loads (MLP>=4).
template <bool RELU>
__global__ void __launch_bounds__(256) k_gather(const float* __restrict__ src) {
    int w    = (blockIdx.x * blockDim.x + threadIdx.x) >> 5;
    int lane = threadIdx.x & 31;
    if (w >= NN) return;
    const int beg = g_rowptr[w];
    const int end = g_rowptr[w + 1];

    float4 a0 = make_float4(0.f, 0.f, 0.f, 0.f);
    float4 a1 = a0, a2 = a0, a3 = a0;
    int i = beg;
    for (; i + 3 < end; i += 4) {
        int c0 = __ldg(g_csr_col + i);
        int c1 = __ldg(g_csr_col + i + 1);
        int c2 = __ldg(g_csr_col + i + 2);
        int c3 = __ldg(g_csr_col + i + 3);
        float4 v0 = __ldg((const float4*)(src + (size_t)c0 * DD) + lane);
        float4 v1 = __ldg((const float4*)(src + (size_t)c1 * DD) + lane);
        float4 v2 = __ldg((const float4*)(src + (size_t)c2 * DD) + lane);
        float4 v3 = __ldg((const float4*)(src + (size_t)c3 * DD) + lane);
        if (RELU) {
            v0.x = fmaxf(v0.x, 0.f); v0.y = fmaxf(v0.y, 0.f);
            v0.z = fmaxf(v0.z, 0.f); v0.w = fmaxf(v0.w, 0.f);
            v1.x = fmaxf(v1.x, 0.f); v1.y = fmaxf(v1.y, 0.f);
            v1.z = fmaxf(v1.z, 0.f); v1.w = fmaxf(v1.w, 0.f);
            v2.x = fmaxf(v2.x, 0.f); v2.y = fmaxf(v2.y, 0.f);
            v2.z = fmaxf(v2.z, 0.f); v2.w = fmaxf(v2.w, 0.f);
            v3.x = fmaxf(v3.x, 0.f); v3.y = fmaxf(v3.y, 0.f);
            v3.z = fmaxf(v3.z, 0.f); v3.w = fmaxf(v3.w, 0.f);
        }
        a0.x += v0.x; a0.y += v0.y; a0.z += v0.z; a0.w += v0.w;
        a1.x += v1.x; a1.y += v1.y; a1.z += v1.z; a1.w += v1.w;
        a2.x += v2.x; a2.y += v2.y; a2.z += v2.z; a2.w += v2.w;
        a3.x += v3.x; a3.y += v3.y; a3.z += v3.z; a3.w += v3.w;
    }
    for (; i < end; i++) {
        int c0 = __ldg(g_csr_col + i);
        float4 v0 = __ldg((const float4*)(src + (size_t)c0 * DD) + lane);
        if (RELU) {
            v0.x = fmaxf(v0.x, 0.f); v0.y = fmaxf(v0.y, 0.f);
            v0.z = fmaxf(v0.z, 0.f); v0.w = fmaxf(v0.w, 0.f);
        }
        a0.x += v0.x; a0.y += v0.y; a0.z += v0.z; a0.w += v0.w;
    }

    float s = g_invdeg[w];
    float4 acc;
    acc.x = ((a0.x + a1.x) + (a2.x + a3.x)) * s;
    acc.y = ((a0.y + a1.y) + (a2.y + a3.y)) * s;
    acc.z = ((a0.z + a1.z) + (a2.z + a3.z)) * s;
    acc.w = ((a0.w + a1.w) + (a2.w + a3.w)) * s;

    // split + swizzled store into agg tile-planes
    int tile  = w >> 7;
    int rowt  = w & 127;
    int chunk = lane >> 4;      // k-half
    int q     = lane & 15;
    char* hb = (char*)g_aggh4 + (size_t)(chunk * NTILES + tile) * 16384;
    char* lb = (char*)g_aggl4 + (size_t)(chunk * NTILES + tile) * 16384;
    st_hl(hb, lb, rowt, q, acc);
}

// ================= mma.sync bf16-split GEMM =================
// out[i][j] = sum_k A[i][k]*B[j][k] + bias[j] (+ h[i][j] if RES)
// A chunks 0-1 and all B chunks are pre-split planes (plain uint4 copies);
// A chunks 2-3 = relu(h) split in-kernel.

#define OFF_BIAS 0
#define OFF_AHI  1024
#define OFF_ALO  (1024 + 16384)
#define OFF_BHI  (1024 + 32768)
#define OFF_BLO  (1024 + 49152)
#define SMEM_GEMM (1024 + 65536)

__device__ __forceinline__ uint32_t s2u(const void* p) {
    uint32_t a;
    asm("{ .reg .u64 t; cvta.to.shared.u64 t, %1; cvt.u32.u64 %0, t; }" : "=r"(a) : "l"(p));
    return a;
}
__device__ __forceinline__ void ldsm4(uint32_t& r0, uint32_t& r1, uint32_t& r2, uint32_t& r3,
                                      uint32_t addr) {
    asm volatile("ldmatrix.sync.aligned.m8n8.x4.shared.b16 {%0,%1,%2,%3}, [%4];"
                 : "=r"(r0), "=r"(r1), "=r"(r2), "=r"(r3) : "r"(addr));
}
__device__ __forceinline__ void mma16816(float* d, const uint32_t* a, const uint32_t* b) {
    asm volatile("mma.sync.aligned.m16n8k16.row.col.f32.bf16.bf16.f32 "
                 "{%0,%1,%2,%3}, {%4,%5,%6,%7}, {%8,%9}, {%0,%1,%2,%3};"
                 : "+f"(d[0]), "+f"(d[1]), "+f"(d[2]), "+f"(d[3])
                 : "r"(a[0]), "r"(a[1]), "r"(a[2]), "r"(a[3]), "r"(b[0]), "r"(b[1]));
}
__device__ __forceinline__ uint32_t tile_addr(uint32_t planeBase, int lane, int r0, int k0) {
    int rr = r0 + (lane & 15);
    int kk = k0 + ((lane >> 4) << 3);
    uint32_t off = rr * 128 + kk * 2;
    return planeBase + (off ^ ((off >> 3) & 0x70));
}

template <bool RELU, bool RES>
__global__ void __launch_bounds__(256)
k_gemm_mma(const float* __restrict__ h, int layer, const float* __restrict__ bias,
           float* __restrict__ out)
{
    extern __shared__ char smem[];
    const uint32_t sb = s2u(smem);
    const int t    = threadIdx.x;
    const int wid  = t >> 5;
    const int lane = t & 31;
    const int blk  = blockIdx.x;
    const int rowBase = blk * 128;
    const int wm = (wid >> 2) * 64;
    const int wn = (wid & 3) * 32;

    if (t < 128) ((float*)(smem + OFF_BIAS))[t] = bias[t];

    float acc[4][4][4];
#pragma unroll
    for (int i = 0; i < 4; i++)
#pragma unroll
        for (int j = 0; j < 4; j++)
#pragma unroll
            for (int q = 0; q < 4; q++) acc[i][j][q] = 0.f;

    uint4* sAh = (uint4*)(smem + OFF_AHI);
    uint4* sAl = (uint4*)(smem + OFF_ALO);
    uint4* sBh = (uint4*)(smem + OFF_BHI);
    uint4* sBl = (uint4*)(smem + OFF_BLO);

    for (int c = 0; c < 4; c++) {
        if (c > 0) __syncthreads();
        const uint4* bh = g_wh4 + (size_t)(layer * 4 + c) * 1024;
        const uint4* bl = g_wl4 + (size_t)(layer * 4 + c) * 1024;
        if (c < 2) {
            const uint4* ah = g_aggh4 + (size_t)(c * NTILES + blk) * 1024;
            const uint4* al = g_aggl4 + (size_t)(c * NTILES + blk) * 1024;
#pragma unroll
            for (int u = 0; u < 4; u++) {
                int i2 = t + u * 256;
                sAh[i2] = __ldg(ah + i2);
                sAl[i2] = __ldg(al + i2);
                sBh[i2] = __ldg(bh + i2);
                sBl[i2] = __ldg(bl + i2);
            }
        } else {
#pragma unroll
            for (int u = 0; u < 8; u++) {
                int idx = t + u * 256;
                int row = idx >> 4, q = idx & 15;
                int gi = rowBase + row;
                float4 va = make_float4(0.f, 0.f, 0.f, 0.f);
                if (gi < NN) {
                    va = __ldg((const float4*)(h + (size_t)gi * DD + (c - 2) * 64) + q);
                    if (RELU) {
                        va.x = fmaxf(va.x, 0.f); va.y = fmaxf(va.y, 0.f);
                        va.z = fmaxf(va.z, 0.f); va.w = fmaxf(va.w, 0.f);
                    }
                }
                st_hl(smem + OFF_AHI, smem + OFF_ALO, row, q, va);
            }
#pragma unroll
            for (int u = 0; u < 4; u++) {
                int i2 = t + u * 256;
                sBh[i2] = __ldg(bh + i2);
                sBl[i2] = __ldg(bl + i2);
            }
        }
        __syncthreads();

        // ---- compute: 4 k-steps of 16 ----
#pragma unroll
        for (int ks = 0; ks < 4; ks++) {
            const int k0 = ks * 16;
            uint32_t bhi[4][2], blo[4][2];
#pragma unroll
            for (int p = 0; p < 2; p++) {
                uint32_t r0, r1, r2, r3;
                ldsm4(r0, r1, r2, r3, tile_addr(sb + OFF_BHI, lane, wn + p * 16, k0));
                bhi[2 * p][0] = r0;     bhi[2 * p][1] = r2;
                bhi[2 * p + 1][0] = r1; bhi[2 * p + 1][1] = r3;
                ldsm4(r0, r1, r2, r3, tile_addr(sb + OFF_BLO, lane, wn + p * 16, k0));
                blo[2 * p][0] = r0;     blo[2 * p][1] = r2;
                blo[2 * p + 1][0] = r1; blo[2 * p + 1][1] = r3;
            }
#pragma unroll
            for (int i = 0; i < 4; i++) {
                uint32_t ahi[4], alo[4];
                ldsm4(ahi[0], ahi[1], ahi[2], ahi[3],
                      tile_addr(sb + OFF_AHI, lane, wm + i * 16, k0));
                ldsm4(alo[0], alo[1], alo[2], alo[3],
                      tile_addr(sb + OFF_ALO, lane, wm + i * 16, k0));
#pragma unroll
                for (int j = 0; j < 4; j++) {
                    mma16816(acc[i][j], ahi, bhi[j]);
                    mma16816(acc[i][j], ahi, blo[j]);
                    mma16816(acc[i][j], alo, bhi[j]);
                }
            }
        }
    }

    // ---- epilogue: bias (+ residual), direct register->gmem ----
    const float* bsh = (const float*)(smem + OFF_BIAS);
    const int tr = lane >> 2;
    const int tc = (lane & 3) * 2;
#pragma unroll
    for (int i = 0; i < 4; i++) {
#pragma unroll
        for (int half = 0; half < 2; half++) {
            int gi = rowBase + wm + i * 16 + tr + half * 8;
            if (gi >= NN) continue;
#pragma unroll
            for (int j = 0; j < 4; j++) {
                int col = wn + j * 8 + tc;
                float2 o;
                o.x = acc[i][j][half * 2]     + bsh[col];
                o.y = acc[i][j][half * 2 + 1] + bsh[col + 1];
                if (RES) {
                    float2 rv = __ldg((const float2*)(h + (size_t)gi * DD + col));
                    o.x += rv.x; o.y += rv.y;
                }
                *(float2*)(out + (size_t)gi * DD + col) = o;
            }
        }
    }
}

// ---------------- launch ----------------
extern "C" void kernel_launch(void* const* d_in, const int* in_sizes, int n_in,
                              void* d_out, int out_size) {
    const float* x    = (const float*)d_in[0];
    const int*   erow = (const int*)  d_in[1];
    const int*   ecol = (const int*)  d_in[2];
    const float* Wl0 = (const float*)d_in[3];
    const float* Wr0 = (const float*)d_in[4];
    const float* b0  = (const float*)d_in[5];
    const float* Wl1 = (const float*)d_in[6];
    const float* Wr1 = (const float*)d_in[7];
    const float* b1  = (const float*)d_in[8];
    const float* Wl2 = (const float*)d_in[9];
    const float* Wr2 = (const float*)d_in[10];
    const float* b2  = (const float*)d_in[11];
    float* out = (float*)d_out;

    float *p_x1 = nullptr, *p_x2 = nullptr;
    cudaGetSymbolAddress((void**)&p_x1, g_x1);
    cudaGetSymbolAddress((void**)&p_x2, g_x2);

    cudaFuncSetAttribute(k_gemm_mma<false, false>,
                         cudaFuncAttributeMaxDynamicSharedMemorySize, SMEM_GEMM);
    cudaFuncSetAttribute(k_gemm_mma<true, true>,
                         cudaFuncAttributeMaxDynamicSharedMemorySize, SMEM_GEMM);

    const int nodeBlocks   = (NN + 255) / 256;
    const int edgeBlocks   = (NE + 255) / 256;
    const int gatherBlocks = (NN * 32 + 255) / 256;   // 6250
    const int gemmBlocks   = NTILES;                  // 391

    // CSR build + W pre-split
    k_zero_deg<<<nodeBlocks, 256>>>();
    k_count_deg<<<edgeBlocks, 256>>>(erow);
    k_buildW<<<32, 256>>>(Wl0, Wr0, 0);
    k_buildW<<<32, 256>>>(Wl1, Wr1, 1);
    k_buildW<<<32, 256>>>(Wl2, Wr2, 2);
    k_scan<<<1, 1024>>>();
    k_fill<<<edgeBlocks, 256>>>(erow, ecol);

    // ---- layer 0: x1 = sage(x) ----
    k_gather<false><<<gatherBlocks, 256>>>(x);
    k_gemm_mma<false, false><<<gemmBlocks, 256, SMEM_GEMM>>>(x, 0, b0, p_x1);

    // ---- layer 1: x2 = sage(relu(x1)) + x1 ----
    k_gather<true><<<gatherBlocks, 256>>>(p_x1);
    k_gemm_mma<true, true><<<gemmBlocks, 256, SMEM_GEMM>>>(p_x1, 1, b1, p_x2);

    // ---- layer 2: out = sage(relu(x2)) + x2 ----
    k_gather<true><<<gatherBlocks, 256>>>(p_x2);
    k_gemm_mma<true, true><<<gemmBlocks, 256, SMEM_GEMM>>>(p_x2, 2, b2, out);
}